// round 1
// baseline (speedup 1.0000x reference)
#include <cuda_runtime.h>
#include <math.h>

#define NN 50000
#define EE 800000
#define DD 96
#define BM 64

// ---------------- scratch (device globals: no allocations allowed) ----------------
__device__ float g_y1[NN * DD];       // x @ Wc1 (self path, already through W2_top)
__device__ float g_h [NN * DD];       // x @ Wc0 (neighbor path, already through W2_bot)
__device__ float g_x1[NN * DD];       // layer-0 output
__device__ int   g_rowptr[NN + 1];
__device__ float g_Wc1[2 * DD * DD];
__device__ float g_Wc0[2 * DD * DD];
__device__ float g_biasA[2 * DD];     // b1 @ W2_top + b2
__device__ float g_biasB[2 * DD];     // b0 @ W2_bot (scaled by in-degree per node)

// ---------------- row_ptr: lower_bound over sorted edge_dst ----------------
__global__ void build_rowptr(const int* __restrict__ dst, int E, int N) {
    int n = blockIdx.x * blockDim.x + threadIdx.x;
    if (n > N) return;
    int lo = 0, hi = E;
    while (lo < hi) {
        int mid = (lo + hi) >> 1;
        if (dst[mid] < n) lo = mid + 1; else hi = mid;
    }
    g_rowptr[n] = lo;
}

// ---------------- combine weights: Wc1 = W1@W2_top, Wc0 = W0@W2_bot ----------------
__global__ void combine_w(const float* __restrict__ W0,
                          const float* __restrict__ W1,
                          const float* __restrict__ W2) {
    int r = blockIdx.x;        // output row 0..95
    int mat = blockIdx.y;      // 0 -> Wc1 (self), 1 -> Wc0 (neighbor)
    int layer = blockIdx.z;
    int f = threadIdx.x;       // output col 0..95
    const float* Wa  = (mat == 0 ? W1 : W0) + layer * DD * DD + r * DD;
    const float* W2p = W2 + layer * 2 * DD * DD + (mat == 0 ? 0 : DD) * DD;
    float acc = 0.f;
#pragma unroll 4
    for (int k = 0; k < DD; k++) acc += Wa[k] * W2p[k * DD + f];
    float* dst = (mat == 0 ? g_Wc1 : g_Wc0) + layer * DD * DD + r * DD + f;
    *dst = acc;
}

__global__ void combine_b(const float* __restrict__ b0,
                          const float* __restrict__ b1,
                          const float* __restrict__ b2,
                          const float* __restrict__ W2) {
    int layer = blockIdx.x;
    int f = threadIdx.x;
    const float* W2p = W2 + layer * 2 * DD * DD;
    float accA = b2[layer * DD + f];
    float accB = 0.f;
#pragma unroll 4
    for (int k = 0; k < DD; k++) {
        accA += b1[layer * DD + k] * W2p[k * DD + f];
        accB += b0[layer * DD + k] * W2p[(DD + k) * DD + f];
    }
    g_biasA[layer * DD + f] = accA;
    g_biasB[layer * DD + f] = accB;
}

// ---------------- dual GEMM: y1 = x@Wc1[layer], h = x@Wc0[layer] ----------------
// blockDim = 384 (1D). Thread owns cols {c, c+48} x 8 rows x 2 matrices = 32 accs.
// smem: Wc1(36KB) + Wc0(36KB) + xtile 64x96 (24KB) = 96KB dynamic.
__global__ __launch_bounds__(384, 2) void dual_gemm(const float* __restrict__ xin,
                                                    int layer, int N) {
    extern __shared__ float sm[];
    float* sW1 = sm;                    // 96*96
    float* sW0 = sm + DD * DD;          // 96*96
    float* sX  = sm + 2 * DD * DD;      // 64*96
    const int tid = threadIdx.x;

    const float4* w1g = (const float4*)(g_Wc1 + layer * DD * DD);
    const float4* w0g = (const float4*)(g_Wc0 + layer * DD * DD);
#pragma unroll
    for (int i = 0; i < 6; i++) {       // 2304 float4 per matrix
        ((float4*)sW1)[tid + i * 384] = w1g[tid + i * 384];
        ((float4*)sW0)[tid + i * 384] = w0g[tid + i * 384];
    }
    const int row0 = blockIdx.x * BM;
#pragma unroll
    for (int i = 0; i < 4; i++) {       // 1536 float4 of x tile
        int idx = tid + i * 384;
        int row = idx / 24;             // 24 float4 per row
        int c4  = idx % 24;
        float4 v = make_float4(0.f, 0.f, 0.f, 0.f);
        if (row0 + row < N) v = ((const float4*)(xin + (size_t)(row0 + row) * DD))[c4];
        ((float4*)sX)[idx] = v;
    }
    __syncthreads();

    const int col  = tid % 48;
    const int ygrp = tid / 48;          // 0..7, owns rows ygrp*8..ygrp*8+7
    float a1a[8], a1b[8], a0a[8], a0b[8];
#pragma unroll
    for (int r = 0; r < 8; r++) { a1a[r] = a1b[r] = a0a[r] = a0b[r] = 0.f; }

#pragma unroll 4
    for (int k = 0; k < DD; k++) {
        float w1a = sW1[k * DD + col], w1b = sW1[k * DD + col + 48];
        float w0a = sW0[k * DD + col], w0b = sW0[k * DD + col + 48];
#pragma unroll
        for (int r = 0; r < 8; r++) {
            float xv = sX[(ygrp * 8 + r) * DD + k];
            a1a[r] += xv * w1a; a1b[r] += xv * w1b;
            a0a[r] += xv * w0a; a0b[r] += xv * w0b;
        }
    }
#pragma unroll
    for (int r = 0; r < 8; r++) {
        int row = row0 + ygrp * 8 + r;
        if (row < N) {
            g_y1[row * DD + col]      = a1a[r];
            g_y1[row * DD + col + 48] = a1b[r];
            g_h [row * DD + col]      = a0a[r];
            g_h [row * DD + col + 48] = a0b[r];
        }
    }
}

// ---------------- aggregation + bias + unbiased-std normalize ----------------
// One warp per node; lane owns features {l, l+32, l+64}.
__global__ __launch_bounds__(256) void agg_norm(const int* __restrict__ esrc,
                                                float* __restrict__ out,
                                                int layer, int N) {
    int warp = (blockIdx.x * blockDim.x + threadIdx.x) >> 5;
    int lane = threadIdx.x & 31;
    if (warp >= N) return;
    const int node = warp;
    const int beg = g_rowptr[node];
    const int end = g_rowptr[node + 1];
    const float* bA = g_biasA + layer * DD;
    const float* bB = g_biasB + layer * DD;
    const float deg = (float)(end - beg);
    const float* yr = g_y1 + (size_t)node * DD;

    float a0 = yr[lane]      + bA[lane]      + deg * bB[lane];
    float a1 = yr[lane + 32] + bA[lane + 32] + deg * bB[lane + 32];
    float a2 = yr[lane + 64] + bA[lane + 64] + deg * bB[lane + 64];

    for (int e = beg; e < end; e++) {
        int s = __ldg(&esrc[e]);
        const float* hr = g_h + (size_t)s * DD;
        a0 += __ldg(&hr[lane]);
        a1 += __ldg(&hr[lane + 32]);
        a2 += __ldg(&hr[lane + 64]);
    }

    float sum = a0 + a1 + a2;
#pragma unroll
    for (int o = 16; o; o >>= 1) sum += __shfl_xor_sync(0xffffffffu, sum, o);
    float mean = sum * (1.0f / 96.0f);
    float d0 = a0 - mean, d1 = a1 - mean, d2 = a2 - mean;
    float sq = d0 * d0 + d1 * d1 + d2 * d2;
#pragma unroll
    for (int o = 16; o; o >>= 1) sq += __shfl_xor_sync(0xffffffffu, sq, o);
    float inv = rsqrtf(sq * (1.0f / 95.0f));   // unbiased: /(96-1)

    float* orow = out + (size_t)node * DD;
    orow[lane]      = a0 * inv;
    orow[lane + 32] = a1 * inv;
    orow[lane + 64] = a2 * inv;
}

// ---------------- host ----------------
extern "C" void kernel_launch(void* const* d_in, const int* in_sizes, int n_in,
                              void* d_out, int out_size) {
    const float* x   = (const float*)d_in[0];
    const float* W0  = (const float*)d_in[1];
    const float* b0  = (const float*)d_in[2];
    const float* W1  = (const float*)d_in[3];
    const float* b1  = (const float*)d_in[4];
    const float* W2  = (const float*)d_in[5];
    const float* b2  = (const float*)d_in[6];
    const int* esrc  = (const int*)d_in[7];
    const int* edst  = (const int*)d_in[8];
    float* out = (float*)d_out;

    const int N = in_sizes[0] / DD;
    const int E = in_sizes[7];

    static bool attr_done = false;
    // idempotent, safe to call every time (not a stream op; no allocation)
    cudaFuncSetAttribute(dual_gemm, cudaFuncAttributeMaxDynamicSharedMemorySize, 98304);
    (void)attr_done;

    float* x1ptr = nullptr;
    cudaGetSymbolAddress((void**)&x1ptr, g_x1);

    build_rowptr<<<(N + 1 + 255) / 256, 256>>>(edst, E, N);
    combine_w<<<dim3(DD, 2, 2), DD>>>(W0, W1, W2);
    combine_b<<<2, DD>>>(b0, b1, b2, W2);

    const int gemm_grid = (N + BM - 1) / BM;
    const int agg_grid  = (N * 32 + 255) / 256;

    // layer 0: x -> g_x1
    dual_gemm<<<gemm_grid, 384, 98304>>>(x, 0, N);
    agg_norm<<<agg_grid, 256>>>(esrc, x1ptr, 0, N);

    // layer 1: g_x1 -> out
    dual_gemm<<<gemm_grid, 384, 98304>>>(x1ptr, 1, N);
    agg_norm<<<agg_grid, 256>>>(esrc, out, 1, N);
}

// round 2
// speedup vs baseline: 1.0114x; 1.0114x over previous
#include <cuda_runtime.h>
#include <math.h>

#define NN 50000
#define EE 800000
#define DD 96
#define BM 64
#define TPB 192   // 24 col-groups x 8 row-groups

// ---------------- scratch (device globals: no allocations allowed) ----------------
__device__ float g_y1[NN * DD];       // x @ Wc1 (self path, through W2_top)
__device__ float g_h [NN * DD];       // x @ Wc0 (neighbor path, through W2_bot)
__device__ float g_x1[NN * DD];       // layer-0 output
__device__ int   g_rowptr[NN + 1];
__device__ float g_Wc1[2 * DD * DD];
__device__ float g_Wc0[2 * DD * DD];
__device__ float g_biasA[2 * DD];     // b1 @ W2_top + b2
__device__ float g_biasB[2 * DD];     // b0 @ W2_bot (scaled by in-degree per node)

// ---------------- row_ptr: lower_bound over sorted edge_dst ----------------
__global__ void build_rowptr(const int* __restrict__ dst, int E, int N) {
    int n = blockIdx.x * blockDim.x + threadIdx.x;
    if (n > N) return;
    int lo = 0, hi = E;
    while (lo < hi) {
        int mid = (lo + hi) >> 1;
        if (dst[mid] < n) lo = mid + 1; else hi = mid;
    }
    g_rowptr[n] = lo;
}

// ---------------- combine weights: Wc1 = W1@W2_top, Wc0 = W0@W2_bot ----------------
__global__ void combine_w(const float* __restrict__ W0,
                          const float* __restrict__ W1,
                          const float* __restrict__ W2) {
    int r = blockIdx.x;        // output row 0..95
    int mat = blockIdx.y;      // 0 -> Wc1 (self), 1 -> Wc0 (neighbor)
    int layer = blockIdx.z;
    int f = threadIdx.x;       // output col 0..95
    const float* Wa  = (mat == 0 ? W1 : W0) + layer * DD * DD + r * DD;
    const float* W2p = W2 + layer * 2 * DD * DD + (mat == 0 ? 0 : DD) * DD;
    float acc = 0.f;
#pragma unroll 4
    for (int k = 0; k < DD; k++) acc += Wa[k] * W2p[k * DD + f];
    float* dst = (mat == 0 ? g_Wc1 : g_Wc0) + layer * DD * DD + r * DD + f;
    *dst = acc;
}

__global__ void combine_b(const float* __restrict__ b0,
                          const float* __restrict__ b1,
                          const float* __restrict__ b2,
                          const float* __restrict__ W2) {
    int layer = blockIdx.x;
    int f = threadIdx.x;
    const float* W2p = W2 + layer * 2 * DD * DD;
    float accA = b2[layer * DD + f];
    float accB = 0.f;
#pragma unroll 4
    for (int k = 0; k < DD; k++) {
        accA += b1[layer * DD + k] * W2p[k * DD + f];
        accB += b0[layer * DD + k] * W2p[(DD + k) * DD + f];
    }
    g_biasA[layer * DD + f] = accA;
    g_biasB[layer * DD + f] = accB;
}

// ---------------- dual GEMM: y1 = x@Wc1[layer], h = x@Wc0[layer] ----------------
// 192 threads. Thread = (colgrp 0..23, rowgrp 0..7). Owns 4 cols x 8 rows x 2 mats
// = 64 accumulators. k-loop in chunks of 4 with float4 LDS on both operands:
// 16 LDS.128 -> 256 FFMA per chunk per thread.
__global__ __launch_bounds__(TPB, 2) void dual_gemm(const float* __restrict__ xin,
                                                    int layer, int N) {
    extern __shared__ float sm[];
    float* sW1 = sm;                    // 96*96
    float* sW0 = sm + DD * DD;          // 96*96
    float* sX  = sm + 2 * DD * DD;      // 64*96
    const int tid = threadIdx.x;

    const float4* w1g = (const float4*)(g_Wc1 + layer * DD * DD);
    const float4* w0g = (const float4*)(g_Wc0 + layer * DD * DD);
#pragma unroll
    for (int i = 0; i < 12; i++) {      // 2304 float4 per matrix
        ((float4*)sW1)[tid + i * TPB] = w1g[tid + i * TPB];
        ((float4*)sW0)[tid + i * TPB] = w0g[tid + i * TPB];
    }
    const int row0 = blockIdx.x * BM;
#pragma unroll
    for (int i = 0; i < 8; i++) {       // 1536 float4 of x tile
        int idx = tid + i * TPB;
        int row = idx / 24;             // 24 float4 per row
        int c4  = idx % 24;
        float4 v = make_float4(0.f, 0.f, 0.f, 0.f);
        if (row0 + row < N) v = ((const float4*)(xin + (size_t)(row0 + row) * DD))[c4];
        ((float4*)sX)[idx] = v;
    }
    __syncthreads();

    const int cg  = tid % 24;           // col group -> cols cg*4 .. cg*4+3
    const int rg  = tid / 24;           // row group -> rows rg*8 .. rg*8+7
    const int col = cg * 4;

    float4 acc1[8], acc0[8];
#pragma unroll
    for (int r = 0; r < 8; r++) {
        acc1[r] = make_float4(0.f, 0.f, 0.f, 0.f);
        acc0[r] = make_float4(0.f, 0.f, 0.f, 0.f);
    }

    for (int k0 = 0; k0 < DD; k0 += 4) {
        float4 xv[8];
#pragma unroll
        for (int r = 0; r < 8; r++)
            xv[r] = *(const float4*)&sX[(rg * 8 + r) * DD + k0];
#pragma unroll
        for (int j = 0; j < 4; j++) {
            float4 w1 = *(const float4*)&sW1[(k0 + j) * DD + col];
            float4 w0 = *(const float4*)&sW0[(k0 + j) * DD + col];
#pragma unroll
            for (int r = 0; r < 8; r++) {
                float xs = (j == 0) ? xv[r].x : (j == 1) ? xv[r].y : (j == 2) ? xv[r].z : xv[r].w;
                acc1[r].x += xs * w1.x; acc1[r].y += xs * w1.y;
                acc1[r].z += xs * w1.z; acc1[r].w += xs * w1.w;
                acc0[r].x += xs * w0.x; acc0[r].y += xs * w0.y;
                acc0[r].z += xs * w0.z; acc0[r].w += xs * w0.w;
            }
        }
    }

#pragma unroll
    for (int r = 0; r < 8; r++) {
        int row = row0 + rg * 8 + r;
        if (row < N) {
            *(float4*)&g_y1[(size_t)row * DD + col] = acc1[r];
            *(float4*)&g_h [(size_t)row * DD + col] = acc0[r];
        }
    }
}

// ---------------- aggregation + bias + unbiased-std normalize ----------------
// One warp per node; lane owns features {l, l+32, l+64}. Edges batched x4 for MLP.
__global__ __launch_bounds__(256) void agg_norm(const int* __restrict__ esrc,
                                                float* __restrict__ out,
                                                int layer, int N) {
    int warp = (blockIdx.x * blockDim.x + threadIdx.x) >> 5;
    int lane = threadIdx.x & 31;
    if (warp >= N) return;
    const int node = warp;
    const int beg = g_rowptr[node];
    const int end = g_rowptr[node + 1];
    const float* bA = g_biasA + layer * DD;
    const float* bB = g_biasB + layer * DD;
    const float deg = (float)(end - beg);
    const float* yr = g_y1 + (size_t)node * DD;

    float a0 = yr[lane]      + bA[lane]      + deg * bB[lane];
    float a1 = yr[lane + 32] + bA[lane + 32] + deg * bB[lane + 32];
    float a2 = yr[lane + 64] + bA[lane + 64] + deg * bB[lane + 64];

    int e = beg;
    for (; e + 4 <= end; e += 4) {
        int s0 = __ldg(&esrc[e]);
        int s1 = __ldg(&esrc[e + 1]);
        int s2 = __ldg(&esrc[e + 2]);
        int s3 = __ldg(&esrc[e + 3]);
        const float* h0 = g_h + (size_t)s0 * DD;
        const float* h1 = g_h + (size_t)s1 * DD;
        const float* h2 = g_h + (size_t)s2 * DD;
        const float* h3 = g_h + (size_t)s3 * DD;
        float t00 = __ldg(&h0[lane]), t01 = __ldg(&h0[lane + 32]), t02 = __ldg(&h0[lane + 64]);
        float t10 = __ldg(&h1[lane]), t11 = __ldg(&h1[lane + 32]), t12 = __ldg(&h1[lane + 64]);
        float t20 = __ldg(&h2[lane]), t21 = __ldg(&h2[lane + 32]), t22 = __ldg(&h2[lane + 64]);
        float t30 = __ldg(&h3[lane]), t31 = __ldg(&h3[lane + 32]), t32 = __ldg(&h3[lane + 64]);
        a0 += (t00 + t10) + (t20 + t30);
        a1 += (t01 + t11) + (t21 + t31);
        a2 += (t02 + t12) + (t22 + t32);
    }
    for (; e < end; e++) {
        int s = __ldg(&esrc[e]);
        const float* hr = g_h + (size_t)s * DD;
        a0 += __ldg(&hr[lane]);
        a1 += __ldg(&hr[lane + 32]);
        a2 += __ldg(&hr[lane + 64]);
    }

    float sum = a0 + a1 + a2;
#pragma unroll
    for (int o = 16; o; o >>= 1) sum += __shfl_xor_sync(0xffffffffu, sum, o);
    float mean = sum * (1.0f / 96.0f);
    float d0 = a0 - mean, d1 = a1 - mean, d2 = a2 - mean;
    float sq = d0 * d0 + d1 * d1 + d2 * d2;
#pragma unroll
    for (int o = 16; o; o >>= 1) sq += __shfl_xor_sync(0xffffffffu, sq, o);
    float inv = rsqrtf(sq * (1.0f / 95.0f));   // unbiased: /(96-1)

    float* orow = out + (size_t)node * DD;
    orow[lane]      = a0 * inv;
    orow[lane + 32] = a1 * inv;
    orow[lane + 64] = a2 * inv;
}

// ---------------- host ----------------
extern "C" void kernel_launch(void* const* d_in, const int* in_sizes, int n_in,
                              void* d_out, int out_size) {
    const float* x   = (const float*)d_in[0];
    const float* W0  = (const float*)d_in[1];
    const float* b0  = (const float*)d_in[2];
    const float* W1  = (const float*)d_in[3];
    const float* b1  = (const float*)d_in[4];
    const float* W2  = (const float*)d_in[5];
    const float* b2  = (const float*)d_in[6];
    const int* esrc  = (const int*)d_in[7];
    const int* edst  = (const int*)d_in[8];
    float* out = (float*)d_out;

    const int N = in_sizes[0] / DD;
    const int E = in_sizes[7];

    cudaFuncSetAttribute(dual_gemm, cudaFuncAttributeMaxDynamicSharedMemorySize, 98304);

    float* x1ptr = nullptr;
    cudaGetSymbolAddress((void**)&x1ptr, g_x1);

    build_rowptr<<<(N + 1 + 255) / 256, 256>>>(edst, E, N);
    combine_w<<<dim3(DD, 2, 2), DD>>>(W0, W1, W2);
    combine_b<<<2, DD>>>(b0, b1, b2, W2);

    const int gemm_grid = (N + BM - 1) / BM;
    const int agg_grid  = (N * 32 + 255) / 256;

    // layer 0: x -> g_x1
    dual_gemm<<<gemm_grid, TPB, 98304>>>(x, 0, N);
    agg_norm<<<agg_grid, 256>>>(esrc, x1ptr, 0, N);

    // layer 1: g_x1 -> out
    dual_gemm<<<gemm_grid, TPB, 98304>>>(x1ptr, 1, N);
    agg_norm<<<agg_grid, 256>>>(esrc, out, 1, N);
}

// round 4
// speedup vs baseline: 1.2472x; 1.2331x over previous
#include <cuda_runtime.h>
#include <cuda_bf16.h>
#include <cstdint>
#include <math.h>

#define NN 50000
#define EE 800000
#define DD 96
#define MT 64                  // GEMM tile rows per block
#define AS 104                 // A smem row stride in bf16 elems (conflict-free)

// ---------------- scratch (device globals) ----------------
__device__ float g_y1[NN * DD];                 // x @ Wc1 (self path through W2_top)
__device__ float g_h [NN * DD];                 // x @ Wc0 (neighbor path through W2_bot)
__device__ __nv_bfloat16 g_xhi[NN * DD];        // layer-1 input, bf16 hi
__device__ __nv_bfloat16 g_xlo[NN * DD];        // layer-1 input, bf16 lo (residual)
__device__ int   g_rowptr[NN + 1];
__device__ float g_Wc[2 * 2 * DD * DD];         // combined weights fp32 [layer][mat][k][n]
// Precomputed B fragments for mma.sync m16n8k16 (row.col):
// [layer][mat][hl: 0=hi,1=lo][kchunk 0..5][ntile 0..11][lane 0..31] -> {b0,b1}
__device__ uint2 g_Bfrag[2][2][2][6][12][32];
__device__ float g_biasA[2 * DD];               // b1 @ W2_top + b2
__device__ float g_biasB[2 * DD];               // b0 @ W2_bot (x in-degree per node)

static __device__ __forceinline__ unsigned short bf16_bits(__nv_bfloat16 h) {
    __nv_bfloat16_raw r = *(__nv_bfloat16_raw*)&h;
    return r.x;
}

// ---------------- row_ptr: lower_bound over sorted edge_dst ----------------
__global__ void build_rowptr(const int* __restrict__ dst, int E, int N) {
    int n = blockIdx.x * blockDim.x + threadIdx.x;
    if (n > N) return;
    int lo = 0, hi = E;
    while (lo < hi) { int mid = (lo + hi) >> 1; if (dst[mid] < n) lo = mid + 1; else hi = mid; }
    g_rowptr[n] = lo;
}

// ---------------- combine weights: Wc = Wa @ W2part (fp32) ----------------
__global__ void combine_w(const float* __restrict__ W0,
                          const float* __restrict__ W1,
                          const float* __restrict__ W2) {
    int r = blockIdx.x;        // k index 0..95
    int mat = blockIdx.y;      // 0 -> self(W1@W2_top), 1 -> neighbor(W0@W2_bot)
    int layer = blockIdx.z;
    int f = threadIdx.x;       // n index 0..95
    const float* Wa  = (mat == 0 ? W1 : W0) + layer * DD * DD + r * DD;
    const float* W2p = W2 + layer * 2 * DD * DD + (mat == 0 ? 0 : DD) * DD;
    float acc = 0.f;
#pragma unroll 4
    for (int k = 0; k < DD; k++) acc += Wa[k] * W2p[k * DD + f];
    g_Wc[((layer * 2 + mat) * DD + r) * DD + f] = acc;
}

__global__ void combine_b(const float* __restrict__ b0,
                          const float* __restrict__ b1,
                          const float* __restrict__ b2,
                          const float* __restrict__ W2) {
    int layer = blockIdx.x;
    int f = threadIdx.x;
    const float* W2p = W2 + layer * 2 * DD * DD;
    float accA = b2[layer * DD + f];
    float accB = 0.f;
#pragma unroll 4
    for (int k = 0; k < DD; k++) {
        accA += b1[layer * DD + k] * W2p[k * DD + f];
        accB += b0[layer * DD + k] * W2p[(DD + k) * DD + f];
    }
    g_biasA[layer * DD + f] = accA;
    g_biasB[layer * DD + f] = accB;
}

// ---------------- pack B fragments (per-lane mma.sync layout) ----------------
// total threads = 2*2*2*6*12*32 = 18432
__global__ void prep_bfrag() {
    int t = blockIdx.x * blockDim.x + threadIdx.x;
    if (t >= 18432) return;
    int lane = t & 31;
    int rest = t >> 5;
    int nt  = rest % 12; rest /= 12;
    int kc  = rest % 6;  rest /= 6;
    int hl  = rest & 1;  rest >>= 1;
    int mat = rest & 1;  rest >>= 1;
    int layer = rest;
    const float* W = g_Wc + (layer * 2 + mat) * DD * DD;  // [k][n]
    int tig = lane & 3, gid = lane >> 2;
    int k0 = kc * 16 + tig * 2;
    int n  = nt * 8 + gid;
    unsigned short v[4];
#pragma unroll
    for (int j = 0; j < 4; j++) {
        int k = k0 + (j >> 1) * 8 + (j & 1);    // k0,k0+1,k0+8,k0+9
        float w = W[k * DD + n];
        __nv_bfloat16 h = __float2bfloat16(w);
        if (hl == 0) v[j] = bf16_bits(h);
        else         v[j] = bf16_bits(__float2bfloat16(w - __bfloat162float(h)));
    }
    uint32_t b0 = (uint32_t)v[0] | ((uint32_t)v[1] << 16);
    uint32_t b1 = (uint32_t)v[2] | ((uint32_t)v[3] << 16);
    g_Bfrag[layer][mat][hl][kc][nt][lane] = make_uint2(b0, b1);
}

// ---------------- HMMA dual GEMM (split-bf16, 3-term compensation) ----------------
// 128 threads = 4 warps; warp w owns rows [w*16, w*16+16) of a 64-row tile.
// Terms: span0 = Ahi@Bhi, span1 = Ahi@Blo, span2 = Alo@Bhi.
__global__ __launch_bounds__(128) void tensor_gemm(const float* __restrict__ x32,
                                                   int layer, int N) {
    __shared__ __nv_bfloat16 sHi[MT * AS];
    __shared__ __nv_bfloat16 sLo[MT * AS];
    const int tid  = threadIdx.x;
    const int row0 = blockIdx.x * MT;

    // ---- fill A tile (64 rows x 96), split fp32 -> bf16 hi/lo ----
#pragma unroll
    for (int i = 0; i < 12; i++) {          // 64*24 chunks / 128 threads
        int idx = tid + i * 128;
        int m = idx / 24, c4 = idx % 24;
        int k = c4 * 4;
        int row = row0 + m;
        uint32_t h01 = 0, h23 = 0, l01 = 0, l23 = 0;
        if (row < N) {
            if (layer == 0) {
                float4 v = ((const float4*)(x32 + (size_t)row * DD))[c4];
                __nv_bfloat16 h0 = __float2bfloat16(v.x), h1 = __float2bfloat16(v.y);
                __nv_bfloat16 h2 = __float2bfloat16(v.z), h3 = __float2bfloat16(v.w);
                h01 = (uint32_t)bf16_bits(h0) | ((uint32_t)bf16_bits(h1) << 16);
                h23 = (uint32_t)bf16_bits(h2) | ((uint32_t)bf16_bits(h3) << 16);
                l01 = (uint32_t)bf16_bits(__float2bfloat16(v.x - __bfloat162float(h0)))
                    | ((uint32_t)bf16_bits(__float2bfloat16(v.y - __bfloat162float(h1))) << 16);
                l23 = (uint32_t)bf16_bits(__float2bfloat16(v.z - __bfloat162float(h2)))
                    | ((uint32_t)bf16_bits(__float2bfloat16(v.w - __bfloat162float(h3))) << 16);
            } else {
                uint2 th = *(const uint2*)(g_xhi + (size_t)row * DD + k);
                uint2 tl = *(const uint2*)(g_xlo + (size_t)row * DD + k);
                h01 = th.x; h23 = th.y; l01 = tl.x; l23 = tl.y;
            }
        }
        *(uint32_t*)&sHi[m * AS + k]     = h01;
        *(uint32_t*)&sHi[m * AS + k + 2] = h23;
        *(uint32_t*)&sLo[m * AS + k]     = l01;
        *(uint32_t*)&sLo[m * AS + k + 2] = l23;
    }
    __syncthreads();

    const int warp = tid >> 5, lane = tid & 31;
    const int gid = lane >> 2, tig = lane & 3;
    const int rbase = warp * 16;

#pragma unroll
    for (int mat = 0; mat < 2; mat++) {
        float c[12][4];
#pragma unroll
        for (int nt = 0; nt < 12; nt++) { c[nt][0] = c[nt][1] = c[nt][2] = c[nt][3] = 0.f; }

#pragma unroll
        for (int span = 0; span < 3; span++) {
            const __nv_bfloat16* As = (span == 2) ? sLo : sHi;
            const int Bhl = (span == 1) ? 1 : 0;
#pragma unroll
            for (int kc = 0; kc < 6; kc++) {
                const int k0 = kc * 16 + tig * 2;
                uint32_t a0 = *(const uint32_t*)&As[(rbase + gid) * AS + k0];
                uint32_t a1 = *(const uint32_t*)&As[(rbase + gid + 8) * AS + k0];
                uint32_t a2 = *(const uint32_t*)&As[(rbase + gid) * AS + k0 + 8];
                uint32_t a3 = *(const uint32_t*)&As[(rbase + gid + 8) * AS + k0 + 8];
                const uint2* bp = &g_Bfrag[layer][mat][Bhl][kc][0][lane];
#pragma unroll
                for (int nt = 0; nt < 12; nt++) {
                    uint2 b = bp[nt * 32];
                    asm volatile(
                        "mma.sync.aligned.m16n8k16.row.col.f32.bf16.bf16.f32 "
                        "{%0,%1,%2,%3}, {%4,%5,%6,%7}, {%8,%9}, {%0,%1,%2,%3};"
                        : "+f"(c[nt][0]), "+f"(c[nt][1]), "+f"(c[nt][2]), "+f"(c[nt][3])
                        : "r"(a0), "r"(a1), "r"(a2), "r"(a3), "r"(b.x), "r"(b.y));
                }
            }
        }

        // ---- epilogue for this mat ----
        float* dst = (mat == 0 ? g_y1 : g_h);
        const int r0 = row0 + rbase + gid;
        const int r1 = r0 + 8;
#pragma unroll
        for (int nt = 0; nt < 12; nt++) {
            int col = nt * 8 + tig * 2;
            if (r0 < N) *(float2*)&dst[(size_t)r0 * DD + col] = make_float2(c[nt][0], c[nt][1]);
            if (r1 < N) *(float2*)&dst[(size_t)r1 * DD + col] = make_float2(c[nt][2], c[nt][3]);
        }
    }
}

// ---------------- aggregation + bias + unbiased-std normalize ----------------
// One warp per node. mode 0: write bf16 hi/lo; mode 1: write fp32 out.
__global__ __launch_bounds__(256) void agg_norm(const int* __restrict__ esrc,
                                                float* __restrict__ outF,
                                                int layer, int mode, int N) {
    int warp = (blockIdx.x * blockDim.x + threadIdx.x) >> 5;
    int lane = threadIdx.x & 31;
    if (warp >= N) return;
    const int node = warp;
    const int beg = g_rowptr[node];
    const int end = g_rowptr[node + 1];
    const float* bA = g_biasA + layer * DD;
    const float* bB = g_biasB + layer * DD;
    const float deg = (float)(end - beg);
    const float* yr = g_y1 + (size_t)node * DD;

    float a0 = yr[lane]      + bA[lane]      + deg * bB[lane];
    float a1 = yr[lane + 32] + bA[lane + 32] + deg * bB[lane + 32];
    float a2 = yr[lane + 64] + bA[lane + 64] + deg * bB[lane + 64];

    int e = beg;
    for (; e + 4 <= end; e += 4) {
        int s0 = __ldg(&esrc[e]);
        int s1 = __ldg(&esrc[e + 1]);
        int s2 = __ldg(&esrc[e + 2]);
        int s3 = __ldg(&esrc[e + 3]);
        const float* h0 = g_h + (size_t)s0 * DD;
        const float* h1 = g_h + (size_t)s1 * DD;
        const float* h2 = g_h + (size_t)s2 * DD;
        const float* h3 = g_h + (size_t)s3 * DD;
        float t00 = __ldg(&h0[lane]), t01 = __ldg(&h0[lane + 32]), t02 = __ldg(&h0[lane + 64]);
        float t10 = __ldg(&h1[lane]), t11 = __ldg(&h1[lane + 32]), t12 = __ldg(&h1[lane + 64]);
        float t20 = __ldg(&h2[lane]), t21 = __ldg(&h2[lane + 32]), t22 = __ldg(&h2[lane + 64]);
        float t30 = __ldg(&h3[lane]), t31 = __ldg(&h3[lane + 32]), t32 = __ldg(&h3[lane + 64]);
        a0 += (t00 + t10) + (t20 + t30);
        a1 += (t01 + t11) + (t21 + t31);
        a2 += (t02 + t12) + (t22 + t32);
    }
    for (; e < end; e++) {
        int s = __ldg(&esrc[e]);
        const float* hr = g_h + (size_t)s * DD;
        a0 += __ldg(&hr[lane]);
        a1 += __ldg(&hr[lane + 32]);
        a2 += __ldg(&hr[lane + 64]);
    }

    float sum = a0 + a1 + a2;
#pragma unroll
    for (int o = 16; o; o >>= 1) sum += __shfl_xor_sync(0xffffffffu, sum, o);
    float mean = sum * (1.0f / 96.0f);
    float d0 = a0 - mean, d1 = a1 - mean, d2 = a2 - mean;
    float sq = d0 * d0 + d1 * d1 + d2 * d2;
#pragma unroll
    for (int o = 16; o; o >>= 1) sq += __shfl_xor_sync(0xffffffffu, sq, o);
    float inv = rsqrtf(sq * (1.0f / 95.0f));

    float v0 = a0 * inv, v1 = a1 * inv, v2 = a2 * inv;
    if (mode == 1) {
        float* orow = outF + (size_t)node * DD;
        orow[lane] = v0; orow[lane + 32] = v1; orow[lane + 64] = v2;
    } else {
        __nv_bfloat16 h0 = __float2bfloat16(v0);
        __nv_bfloat16 h1 = __float2bfloat16(v1);
        __nv_bfloat16 h2 = __float2bfloat16(v2);
        size_t base = (size_t)node * DD;
        g_xhi[base + lane]      = h0;
        g_xhi[base + lane + 32] = h1;
        g_xhi[base + lane + 64] = h2;
        g_xlo[base + lane]      = __float2bfloat16(v0 - __bfloat162float(h0));
        g_xlo[base + lane + 32] = __float2bfloat16(v1 - __bfloat162float(h1));
        g_xlo[base + lane + 64] = __float2bfloat16(v2 - __bfloat162float(h2));
    }
}

// ---------------- host ----------------
extern "C" void kernel_launch(void* const* d_in, const int* in_sizes, int n_in,
                              void* d_out, int out_size) {
    const float* x   = (const float*)d_in[0];
    const float* W0  = (const float*)d_in[1];
    const float* b0  = (const float*)d_in[2];
    const float* W1  = (const float*)d_in[3];
    const float* b1  = (const float*)d_in[4];
    const float* W2  = (const float*)d_in[5];
    const float* b2  = (const float*)d_in[6];
    const int* esrc  = (const int*)d_in[7];
    const int* edst  = (const int*)d_in[8];
    float* out = (float*)d_out;

    const int N = in_sizes[0] / DD;
    const int E = in_sizes[7];

    build_rowptr<<<(N + 1 + 255) / 256, 256>>>(edst, E, N);
    combine_w<<<dim3(DD, 2, 2), DD>>>(W0, W1, W2);
    combine_b<<<2, DD>>>(b0, b1, b2, W2);
    prep_bfrag<<<(18432 + 255) / 256, 256>>>();

    const int gemm_grid = (N + MT - 1) / MT;
    const int agg_grid  = (N * 32 + 255) / 256;

    // layer 0: x fp32 -> GEMM -> agg_norm writes bf16 hi/lo
    tensor_gemm<<<gemm_grid, 128>>>(x, 0, N);
    agg_norm<<<agg_grid, 256>>>(esrc, nullptr, 0, 0, N);

    // layer 1: bf16 hi/lo -> GEMM -> agg_norm writes fp32 out
    tensor_gemm<<<gemm_grid, 128>>>(nullptr, 1, N);
    agg_norm<<<agg_grid, 256>>>(esrc, out, 1, 1, N);
}